// round 5
// baseline (speedup 1.0000x reference)
#include <cuda_runtime.h>
#include <cstdint>

#define NUM_E      5
#define NTOK       (16 * 2048)
#define OUTF       512
#define MAXF       128
#define BM         128
#define BN         128
#define MAX_ROWS   (NTOK + NUM_E * BM)
#define MAX_MTILES (MAX_ROWS / BM)
#define SMEM_BYTES ((BM + BN) * 132 * 4)

// ---------------- scratch (static device globals; zero-initialized at load) ---------------
__device__ int g_counts[NUM_E];        // invariant: zero at entry of k_count (reset by k_offsets)
__device__ int g_offsets[NUM_E + 1];   // 128-aligned exclusive scan of counts
__device__ int g_slot[NTOK];           // slot of token within its expert bucket
__device__ int g_rows[MAX_ROWS];       // gathered row -> token id (-1 = padding)

// in_feat_size may be int32 or int64 depending on jax x64 config. Values are in
// {8,16,32,64,128} (never 0), little-endian: if int64, word[1] (high half of elem 0) is 0.
__device__ __forceinline__ int expert_of(const int* __restrict__ feat, int t) {
    int is64 = (feat[1] == 0) ? 1 : 0;
    int v = feat[is64 ? (t << 1) : t];
    return __ffs(v) - 4;   // 8->0, 16->1, 32->2, 64->3, 128->4
}

__global__ void k_count(const int* __restrict__ feat) {
    int t = blockIdx.x * blockDim.x + threadIdx.x;
    if (t >= NTOK) return;
    int e = expert_of(feat, t);
    g_slot[t] = atomicAdd(&g_counts[e], 1);
}

__global__ void k_offsets() {
    if (threadIdx.x == 0) {
        int acc = 0;
        for (int e = 0; e < NUM_E; e++) {
            g_offsets[e] = acc;
            acc += (g_counts[e] + BM - 1) / BM * BM;   // pad each expert to BM rows
        }
        g_offsets[NUM_E] = acc;
    }
    __syncthreads();
    // mark padding rows
    for (int e = 0; e < NUM_E; e++) {
        int s  = g_offsets[e] + g_counts[e];
        int en = g_offsets[e + 1];
        for (int i = s + (int)threadIdx.x; i < en; i += blockDim.x) g_rows[i] = -1;
    }
    __syncthreads();
    // reset counts so the next graph replay sees zeros
    if (threadIdx.x < NUM_E) g_counts[threadIdx.x] = 0;
}

__global__ void k_scatter(const int* __restrict__ feat) {
    int t = blockIdx.x * blockDim.x + threadIdx.x;
    if (t >= NTOK) return;
    int e = expert_of(feat, t);
    g_rows[g_offsets[e] + g_slot[t]] = t;
}

// ---------------- 3xTF32 GEMM ----------------
__device__ __forceinline__ void split_tf32(float f, uint32_t& hi, uint32_t& lo) {
    asm("cvt.rna.tf32.f32 %0, %1;" : "=r"(hi) : "f"(f));
    float lf = f - __uint_as_float(hi);                 // exact in fp32
    asm("cvt.rna.tf32.f32 %0, %1;" : "=r"(lo) : "f"(lf));
}

__device__ __forceinline__ void mma8(float* c, const uint32_t* a, const uint32_t* b) {
    asm volatile(
        "mma.sync.aligned.m16n8k8.row.col.f32.tf32.tf32.f32 "
        "{%0,%1,%2,%3}, {%4,%5,%6,%7}, {%8,%9}, {%0,%1,%2,%3};\n"
        : "+f"(c[0]), "+f"(c[1]), "+f"(c[2]), "+f"(c[3])
        : "r"(a[0]), "r"(a[1]), "r"(a[2]), "r"(a[3]), "r"(b[0]), "r"(b[1]));
}

__global__ void __launch_bounds__(256, 1)
k_gemm(const float* __restrict__ x, const float* __restrict__ w,
       const float* __restrict__ bias, float* __restrict__ out) {
    extern __shared__ float sm[];
    const int row0 = blockIdx.x * BM;
    if (row0 >= g_offsets[NUM_E]) return;

    int e = 0;
#pragma unroll
    for (int i = 1; i < NUM_E; i++) e += (row0 >= g_offsets[i]);
    const int K     = 8 << e;       // expert's real K
    const int lds   = K + 4;        // padded smem stride (floats); lds%32 in {12,20,4} -> conflict-free
    const int kq    = K >> 2;       // float4 per row
    const int kq_sh = e + 1;        // log2(kq)

    float* sA = sm;                 // [BM][lds]
    float* sB = sm + BM * 132;      // [BN][lds]
    const int tx = threadIdx.x;

    // ---- load gathered A tile (x rows of this expert), only first K features ----
    for (int i = tx; i < BM * kq; i += 256) {
        int r = i >> kq_sh, c = i & (kq - 1);
        int tok = g_rows[row0 + r];
        tok = tok < 0 ? 0 : tok;    // padding rows: load token 0, result discarded
        float4 v = *((const float4*)(x + (size_t)tok * MAXF) + c);
        *(float4*)(sA + r * lds + (c << 2)) = v;
    }

    const int warp = tx >> 5, lane = tx & 31;
    const int wm = warp >> 2, wn = warp & 3;     // 2x4 warps -> 64x32 warp tiles
    const int grp = lane >> 2, qid = lane & 3;

    // loop over all 4 N-tiles reusing sA (x read once per token)
    for (int nt = 0; nt < OUTF / BN; nt++) {
        const int n0 = nt * BN;
        __syncthreads();   // A stores done (iter 0) / previous compute done reading sB

        const float* wb = w + ((size_t)e * OUTF + n0) * MAXF;
        for (int i = tx; i < BN * kq; i += 256) {
            int r = i >> kq_sh, c = i & (kq - 1);
            float4 v = *((const float4*)(wb + r * MAXF) + c);
            *(float4*)(sB + r * lds + (c << 2)) = v;
        }
        __syncthreads();

        float acc[4][4][4];
#pragma unroll
        for (int a0 = 0; a0 < 4; a0++)
#pragma unroll
            for (int b0 = 0; b0 < 4; b0++)
#pragma unroll
                for (int c0 = 0; c0 < 4; c0++) acc[a0][b0][c0] = 0.f;

        for (int ks = 0; ks < K; ks += 8) {
            uint32_t ah[4][4], al[4][4];
#pragma unroll
            for (int mf = 0; mf < 4; mf++) {
                const float* ap = sA + (wm * 64 + mf * 16 + grp) * lds + ks + qid;
                split_tf32(ap[0],           ah[mf][0], al[mf][0]);
                split_tf32(ap[8 * lds],     ah[mf][1], al[mf][1]);
                split_tf32(ap[4],           ah[mf][2], al[mf][2]);
                split_tf32(ap[8 * lds + 4], ah[mf][3], al[mf][3]);
            }
#pragma unroll
            for (int nf = 0; nf < 4; nf++) {
                const float* bp = sB + (wn * 32 + nf * 8 + grp) * lds + ks + qid;
                uint32_t bh[2], bl[2];
                split_tf32(bp[0], bh[0], bl[0]);
                split_tf32(bp[4], bh[1], bl[1]);
#pragma unroll
                for (int mf = 0; mf < 4; mf++) {
                    mma8(acc[mf][nf], ah[mf], bh);   // hi*hi
                    mma8(acc[mf][nf], al[mf], bh);   // lo*hi
                    mma8(acc[mf][nf], ah[mf], bl);   // hi*lo
                }
            }
        }

        // ---- scatter epilogue: out[token] = acc + bias[e] ----
#pragma unroll
        for (int mf = 0; mf < 4; mf++) {
            int r0 = row0 + wm * 64 + mf * 16 + grp;
            int t0 = g_rows[r0];
            int t1 = g_rows[r0 + 8];
#pragma unroll
            for (int nf = 0; nf < 4; nf++) {
                int c = n0 + wn * 32 + nf * 8 + (qid << 1);
                float2 bv = *(const float2*)(bias + e * OUTF + c);
                if (t0 >= 0) {
                    float2 o = make_float2(acc[mf][nf][0] + bv.x, acc[mf][nf][1] + bv.y);
                    *(float2*)(out + (size_t)t0 * OUTF + c) = o;
                }
                if (t1 >= 0) {
                    float2 o = make_float2(acc[mf][nf][2] + bv.x, acc[mf][nf][3] + bv.y);
                    *(float2*)(out + (size_t)t1 * OUTF + c) = o;
                }
            }
        }
    }
}

// ---------------- launch ----------------
extern "C" void kernel_launch(void* const* d_in, const int* in_sizes, int n_in,
                              void* d_out, int out_size) {
    (void)in_sizes; (void)n_in; (void)out_size;
    const float* x    = (const float*)d_in[0];
    const int*   feat = (const int*)d_in[1];     // int32 or int64, auto-detected on device
    const float* w    = (const float*)d_in[2];
    const float* b    = (const float*)d_in[3];
    float*       out  = (float*)d_out;

    cudaFuncSetAttribute(k_gemm, cudaFuncAttributeMaxDynamicSharedMemorySize, SMEM_BYTES);

    k_count  <<<(NTOK + 255) / 256, 256>>>(feat);
    k_offsets<<<1, 256>>>();
    k_scatter<<<(NTOK + 255) / 256, 256>>>(feat);
    k_gemm   <<<MAX_MTILES, 256, SMEM_BYTES>>>(x, w, b, out);
}